// round 1
// baseline (speedup 1.0000x reference)
#include <cuda_runtime.h>
#include <cuda_bf16.h>
#include <math.h>

// Problem constants
#define BATCH   4
#define SEQ     4096
#define HID     1024
#define NHEAD   16
#define HD      64
#define CSZ     16
#define MROWS   (BATCH*SEQ)        // 16384
#define NCHUNK  (SEQ/CSZ)          // 256 per batch
#define BNCH    (BATCH*NCHUNK)     // 1024 chunk-blocks total

// ---------------- scratch (static device globals; no allocation) ----------------
__device__ float g_xp[MROWS*HID];        // 64 MB  post-GEMM1 projection
__device__ float g_a[MROWS*NHEAD];       //  1 MB  decay a = tanh(eig)*alpha
__device__ float g_b[MROWS*HID];         // 64 MB  b = beta * x_heads
__device__ float g_cum[MROWS*NHEAD];     //  1 MB  within-chunk cumprod per (pos, head)
__device__ float g_contrib[MROWS*HID];   // 64 MB  within-chunk contribution -> h_all (in place)
__device__ float g_C[BNCH*NHEAD];        // per-chunk total decay
__device__ float g_E[BNCH*HID];          // per-chunk end contribution
__device__ float g_carry[BNCH*HID];      // carry into each chunk

// ---------------- GEMM: C[m,n] = sum_k A[m,k]*B[n,k]  (NT, row-major) ----------------
// 128x128 tile, BK=8, 8x8 per thread, 256 threads.
__global__ __launch_bounds__(256) void sgemm_nt_kernel(
    const float* __restrict__ A, const float* __restrict__ B, float* __restrict__ C,
    int M, int N, int K)
{
    __shared__ float As[8][128];
    __shared__ float Bs[8][128];

    const int tid  = threadIdx.x;
    const int arow = tid >> 1;          // 0..127
    const int acol = (tid & 1) << 2;    // 0 or 4
    const int trow = tid >> 4;          // 0..15
    const int tcol = tid & 15;          // 0..15

    const float* Ab = A + (size_t)(blockIdx.y * 128) * K;
    const float* Bb = B + (size_t)(blockIdx.x * 128) * K;

    float acc[8][8];
#pragma unroll
    for (int i = 0; i < 8; i++)
#pragma unroll
        for (int j = 0; j < 8; j++) acc[i][j] = 0.f;

    for (int k0 = 0; k0 < K; k0 += 8) {
        float4 av = *(const float4*)(Ab + (size_t)arow * K + k0 + acol);
        float4 bv = *(const float4*)(Bb + (size_t)arow * K + k0 + acol);
        As[acol + 0][arow] = av.x; As[acol + 1][arow] = av.y;
        As[acol + 2][arow] = av.z; As[acol + 3][arow] = av.w;
        Bs[acol + 0][arow] = bv.x; Bs[acol + 1][arow] = bv.y;
        Bs[acol + 2][arow] = bv.z; Bs[acol + 3][arow] = bv.w;
        __syncthreads();

#pragma unroll
        for (int k = 0; k < 8; k++) {
            float4 a0 = *(const float4*)&As[k][trow * 8];
            float4 a1 = *(const float4*)&As[k][trow * 8 + 4];
            float4 b0 = *(const float4*)&Bs[k][tcol * 8];
            float4 b1 = *(const float4*)&Bs[k][tcol * 8 + 4];
            float rm[8] = {a0.x, a0.y, a0.z, a0.w, a1.x, a1.y, a1.z, a1.w};
            float rn[8] = {b0.x, b0.y, b0.z, b0.w, b1.x, b1.y, b1.z, b1.w};
#pragma unroll
            for (int i = 0; i < 8; i++)
#pragma unroll
                for (int j = 0; j < 8; j++)
                    acc[i][j] = fmaf(rm[i], rn[j], acc[i][j]);
        }
        __syncthreads();
    }

#pragma unroll
    for (int i = 0; i < 8; i++) {
        float* cp = C + (size_t)(blockIdx.y * 128 + trow * 8 + i) * N + blockIdx.x * 128 + tcol * 8;
        *(float4*)(cp)     = make_float4(acc[i][0], acc[i][1], acc[i][2], acc[i][3]);
        *(float4*)(cp + 4) = make_float4(acc[i][4], acc[i][5], acc[i][6], acc[i][7]);
    }
}

// ---------------- LayerNorm + gates + a/b construction (one block per row) ----------------
__global__ __launch_bounds__(256) void ln_gates_kernel(
    const float* __restrict__ xp, const float* __restrict__ ln_g, const float* __restrict__ ln_b,
    const float* __restrict__ Wg, const float* __restrict__ bg, const float* __restrict__ eig_raw,
    float* __restrict__ a_out, float* __restrict__ b_out)
{
    const int r = blockIdx.x;
    const int t = threadIdx.x;
    const int w = t >> 5, lane = t & 31;

    __shared__ float sx[HID];
    __shared__ float red[8], red2[8];
    __shared__ float gsm[32];
    __shared__ float sbeta[16];
    __shared__ float s_mean, s_rstd;

    float4 x4 = reinterpret_cast<const float4*>(xp + (size_t)r * HID)[t];
    float sum = x4.x + x4.y + x4.z + x4.w;
    float ss  = x4.x * x4.x + x4.y * x4.y + x4.z * x4.z + x4.w * x4.w;
#pragma unroll
    for (int o = 16; o > 0; o >>= 1) {
        sum += __shfl_xor_sync(0xffffffffu, sum, o);
        ss  += __shfl_xor_sync(0xffffffffu, ss, o);
    }
    if (lane == 0) { red[w] = sum; red2[w] = ss; }
    __syncthreads();
    if (t == 0) {
        float S = 0.f, S2 = 0.f;
#pragma unroll
        for (int i = 0; i < 8; i++) { S += red[i]; S2 += red2[i]; }
        float mu  = S * (1.f / HID);
        float var = S2 * (1.f / HID) - mu * mu;
        s_mean = mu;
        s_rstd = rsqrtf(var + 1e-5f);
    }
    __syncthreads();
    const float mu = s_mean, rs = s_rstd;

    float4 g4 = reinterpret_cast<const float4*>(ln_g)[t];
    float4 o4 = reinterpret_cast<const float4*>(ln_b)[t];
    float4 xn;
    xn.x = (x4.x - mu) * rs * g4.x + o4.x;
    xn.y = (x4.y - mu) * rs * g4.y + o4.y;
    xn.z = (x4.z - mu) * rs * g4.z + o4.z;
    xn.w = (x4.w - mu) * rs * g4.w + o4.w;
    reinterpret_cast<float4*>(sx)[t] = xn;
    __syncthreads();

    // gates: 8 warps x 4 gates each = 32 dot products of length 1024
#pragma unroll
    for (int q = 0; q < 4; q++) {
        int g = w * 4 + q;
        const float* wrow = Wg + (size_t)g * HID;
        float s = 0.f;
#pragma unroll 8
        for (int j = lane; j < HID; j += 32) s = fmaf(sx[j], wrow[j], s);
#pragma unroll
        for (int o = 16; o > 0; o >>= 1) s += __shfl_xor_sync(0xffffffffu, s, o);
        if (lane == 0) gsm[g] = s + bg[g];
    }
    __syncthreads();

    if (t < 16) {
        float alpha = 1.f / (1.f + expf(-gsm[t]));
        a_out[(size_t)r * NHEAD + t] = tanhf(eig_raw[t]) * alpha;
        sbeta[t] = 1.f / (1.f + expf(-gsm[16 + t]));
    }
    __syncthreads();

    float beta = sbeta[t >> 4];   // head of element t*4 (..t*4+3, all same head since 4|64)
    float4 bo;
    bo.x = beta * xn.x; bo.y = beta * xn.y; bo.z = beta * xn.z; bo.w = beta * xn.w;
    reinterpret_cast<float4*>(b_out + (size_t)r * HID)[t] = bo;
}

// ---------------- scan pass 1: per-chunk contribution with reference masking ----------------
// one block per (batch,chunk,head): blk = (b*NCHUNK+n)*NHEAD + h ; 64 threads = head dims
__global__ __launch_bounds__(64) void scan1_kernel(
    const float* __restrict__ a_buf, const float* __restrict__ b_buf,
    float* __restrict__ contrib, float* __restrict__ cum_out,
    float* __restrict__ Cc, float* __restrict__ Ee)
{
    const int blk = blockIdx.x;
    const int h   = blk & 15;
    const int bn  = blk >> 4;            // b*NCHUNK + n
    const int base_pos = bn * CSZ;       // == b*SEQ + n*CSZ
    const int d = threadIdx.x;

    __shared__ float s_a[CSZ];
    __shared__ float s_cum[CSZ];
    __shared__ float s_inv[CSZ];         // mask_j ? 1/cum_pad_j : 0

    if (d < CSZ) s_a[d] = a_buf[(size_t)(base_pos + d) * NHEAD + h];
    __syncthreads();
    if (d == 0) {
        float c = 1.f;
#pragma unroll
        for (int j = 0; j < CSZ; j++) {
            float cp = c;                        // cum_pad_j
            c = c * s_a[j];                      // cum_j (fp32 sequential, matches cumprod)
            s_cum[j] = c;
            s_inv[j] = (fabsf(cp) > 1e-8f) ? (1.f / cp) : 0.f;
            cum_out[(size_t)(base_pos + j) * NHEAD + h] = c;
        }
    }
    __syncthreads();

    float Q = 0.f;
    float hc = 0.f;
#pragma unroll
    for (int j = 0; j < CSZ; j++) {
        size_t idx = (size_t)(base_pos + j) * HID + h * HD + d;
        float bv = b_buf[idx];
        hc = fmaf(s_cum[j], Q, bv);              // h_contrib_j = b_j + cum_j * sum_{i<j} mask_i b_i/cum_pad_i
        contrib[idx] = hc;
        Q = fmaf(bv, s_inv[j], Q);
    }
    Ee[(size_t)bn * HID + h * HD + d] = hc;      // chunk-end contribution
    if (d == 0) Cc[(size_t)bn * NHEAD + h] = s_cum[CSZ - 1];
}

// ---------------- scan pass 2: sequential carry over 256 chunks per channel ----------------
__global__ __launch_bounds__(128) void scan2_kernel(
    const float* __restrict__ Cc, const float* __restrict__ Ee, float* __restrict__ carry)
{
    int ch = blockIdx.x * blockDim.x + threadIdx.x;  // 0..4095
    int b = ch >> 10;
    int c = ch & 1023;
    int h = c >> 6;
    float hcar = 0.f;
    for (int n = 0; n < NCHUNK; n++) {
        int bn = b * NCHUNK + n;
        carry[(size_t)bn * HID + c] = hcar;
        hcar = fmaf(Cc[(size_t)bn * NHEAD + h], hcar, Ee[(size_t)bn * HID + c]);
    }
}

// ---------------- scan pass 3: recombine h_all = cum*carry + contrib (in place); emit h_final ----------------
__global__ __launch_bounds__(256) void scan3_kernel(
    const float* __restrict__ cum, const float* __restrict__ carry,
    float* __restrict__ hall, float* __restrict__ h_final)
{
    int g = blockIdx.x * blockDim.x + threadIdx.x;   // float4 index, 4.19M total
    int pos = g >> 8;                                 // element base = g*4; pos = base/1024
    int c0  = (g & 255) << 2;                         // 0..1020
    int h   = c0 >> 6;
    int bn  = pos >> 4;

    float cm = cum[(size_t)pos * NHEAD + h];
    float4 cr = reinterpret_cast<const float4*>(carry + (size_t)bn * HID)[c0 >> 2];
    float4 hv = reinterpret_cast<float4*>(hall)[g];
    hv.x = fmaf(cm, cr.x, hv.x);
    hv.y = fmaf(cm, cr.y, hv.y);
    hv.z = fmaf(cm, cr.z, hv.z);
    hv.w = fmaf(cm, cr.w, hv.w);
    reinterpret_cast<float4*>(hall)[g] = hv;
    if ((pos & (SEQ - 1)) == SEQ - 1) {
        int b = pos >> 12;
        reinterpret_cast<float4*>(h_final + (size_t)b * HID)[c0 >> 2] = hv;
    }
}

// ---------------- launch ----------------
extern "C" void kernel_launch(void* const* d_in, const int* in_sizes, int n_in,
                              void* d_out, int out_size)
{
    const float* x       = (const float*)d_in[0];
    const float* W_in    = (const float*)d_in[1];
    const float* ln_g    = (const float*)d_in[2];
    const float* ln_b    = (const float*)d_in[3];
    const float* W_gate  = (const float*)d_in[4];
    const float* b_gate  = (const float*)d_in[5];
    const float* eig_raw = (const float*)d_in[6];
    const float* W_out   = (const float*)d_in[7];

    float* out     = (float*)d_out;                  // [B,S,HID]
    float* h_final = out + (size_t)MROWS * HID;      // [B,HID] appended

    float *xp, *ab, *bb, *cum, *contrib, *Cc, *Ee, *carry;
    cudaGetSymbolAddress((void**)&xp,      g_xp);
    cudaGetSymbolAddress((void**)&ab,      g_a);
    cudaGetSymbolAddress((void**)&bb,      g_b);
    cudaGetSymbolAddress((void**)&cum,     g_cum);
    cudaGetSymbolAddress((void**)&contrib, g_contrib);
    cudaGetSymbolAddress((void**)&Cc,      g_C);
    cudaGetSymbolAddress((void**)&Ee,      g_E);
    cudaGetSymbolAddress((void**)&carry,   g_carry);

    // 1) xp = x @ W_in^T
    sgemm_nt_kernel<<<dim3(HID / 128, MROWS / 128), 256>>>(x, W_in, xp, MROWS, HID, HID);
    // 2) LN + gates -> a, b
    ln_gates_kernel<<<MROWS, 256>>>(xp, ln_g, ln_b, W_gate, b_gate, eig_raw, ab, bb);
    // 3) chunked scan with reference masking
    scan1_kernel<<<BNCH * NHEAD, 64>>>(ab, bb, contrib, cum, Cc, Ee);
    scan2_kernel<<<(BATCH * HID) / 128, 128>>>(Cc, Ee, carry);
    scan3_kernel<<<(MROWS * HID / 4) / 256, 256>>>(cum, carry, contrib, h_final);
    // 4) output = h_all @ W_out^T
    sgemm_nt_kernel<<<dim3(HID / 128, MROWS / 128), 256>>>(contrib, W_out, out, MROWS, HID, HID);
}

// round 3
// speedup vs baseline: 2.9522x; 2.9522x over previous
#include <cuda_runtime.h>
#include <cuda_bf16.h>
#include <math.h>
#include <stdint.h>

// ---------------- problem constants ----------------
#define BATCH   4
#define SEQ     4096
#define HID     1024
#define NHEAD   16
#define HD      64
#define CSZ     16
#define MROWS   (BATCH*SEQ)        // 16384
#define NCHUNK  (SEQ/CSZ)          // 256
#define BNCH    (BATCH*NCHUNK)     // 1024
#define KTOT    3072               // 3 * HID (hi|lo|hi split-precision)
#define BK      64                 // bf16 K per stage (128 bytes/row)
#define KI      (KTOT/BK)          // 48
#define NSTG    4
#define STG_BYTES 32768            // A 16KB + B 16KB
#define GEMM_SMEM (NSTG*STG_BYTES) // 128 KB

// ---------------- scratch (static device globals) ----------------
__device__ __align__(16) __nv_bfloat16 g_Abuf[(size_t)MROWS*KTOT]; // 96 MB
__device__ __align__(16) __nv_bfloat16 g_Bbuf[(size_t)HID*KTOT];   // 6 MB
__device__ float g_xp[MROWS*HID];
__device__ float g_xn[MROWS*HID];
__device__ float g_contrib[MROWS*HID];
__device__ float g_a[MROWS*NHEAD];
__device__ float g_beta[MROWS*NHEAD];
__device__ float g_cum[MROWS*NHEAD];
__device__ float g_C[BNCH*NHEAD];
__device__ float g_E[BNCH*HID];
__device__ float g_carry[BNCH*HID];
__device__ float g_P2[BATCH*HID*16];
__device__ float g_E2[BATCH*HID*16];
__device__ float g_G2[BATCH*HID*16];

// ---------------- PTX helpers (all sm_80-level: compile-safe on compute_103) ----------------
__device__ __forceinline__ uint32_t smem_u32(const void* p) {
    uint32_t a;
    asm("{ .reg .u64 t; cvta.to.shared.u64 t, %1; cvt.u32.u64 %0, t; }" : "=r"(a) : "l"(p));
    return a;
}
#define CP_COMMIT() asm volatile("cp.async.commit_group;" ::: "memory")
#define CP_WAIT(N)  asm volatile("cp.async.wait_group %0;" :: "n"(N) : "memory")
__device__ __forceinline__ void cp_async16(uint32_t s, const void* g) {
    asm volatile("cp.async.cg.shared.global [%0], [%1], 16;" :: "r"(s), "l"(g) : "memory");
}
__device__ __forceinline__ void ldsm_x4(uint32_t& r0, uint32_t& r1, uint32_t& r2, uint32_t& r3, uint32_t addr) {
    asm volatile("ldmatrix.sync.aligned.m8n8.x4.shared.b16 {%0,%1,%2,%3}, [%4];"
                 : "=r"(r0), "=r"(r1), "=r"(r2), "=r"(r3) : "r"(addr));
}
__device__ __forceinline__ void mma16816(float& c0, float& c1, float& c2, float& c3,
                                         uint32_t a0, uint32_t a1, uint32_t a2, uint32_t a3,
                                         uint32_t b0, uint32_t b1) {
    asm volatile("mma.sync.aligned.m16n8k16.row.col.f32.bf16.bf16.f32 "
                 "{%0,%1,%2,%3}, {%4,%5,%6,%7}, {%8,%9}, {%0,%1,%2,%3};"
                 : "+f"(c0), "+f"(c1), "+f"(c2), "+f"(c3)
                 : "r"(a0), "r"(a1), "r"(a2), "r"(a3), "r"(b0), "r"(b1));
}
// xor-swizzle for 128B rows: chunk(bits 4-6) ^= row(bits 7-9)
__device__ __forceinline__ uint32_t swz(uint32_t off) { return off ^ ((off >> 3) & 0x70); }

// ---------------- fp32 -> bf16 split-triplet conversion ----------------
// MODE 0 (A side): cols [0..1023]=hi, [1024..2047]=lo, [2048..3071]=hi
// MODE 1 (B side): cols [0..1023]=hi, [1024..2047]=hi, [2048..3071]=lo
template<int MODE>
__global__ __launch_bounds__(256) void convert_tri_kernel(
    const float* __restrict__ in, __nv_bfloat16* __restrict__ out)
{
    int g = blockIdx.x * 256 + threadIdx.x;       // float4 index
    int row = g >> 8;
    int c0  = (g & 255) << 2;
    float4 v = reinterpret_cast<const float4*>(in)[g];
    float f[4] = {v.x, v.y, v.z, v.w};
    union { __nv_bfloat16 b[4]; uint2 u; } H, L;
#pragma unroll
    for (int i = 0; i < 4; i++) {
        H.b[i] = __float2bfloat16_rn(f[i]);
        L.b[i] = __float2bfloat16_rn(f[i] - __bfloat162float(H.b[i]));
    }
    size_t base = (size_t)row * KTOT + c0;
    *reinterpret_cast<uint2*>(out + base)        = H.u;
    *reinterpret_cast<uint2*>(out + base + 1024) = (MODE == 0) ? L.u : H.u;
    *reinterpret_cast<uint2*>(out + base + 2048) = (MODE == 0) ? H.u : L.u;
}

// ---------------- mma.sync bf16 GEMM: C[m,n] = sum_k A[m,k]*B[n,k], K=3072 ----------------
// 128x128 tile, BK=64, 4-stage cp.async, 256 threads (8 warps, 32x64 each).
__device__ __forceinline__ void load_stage(const __nv_bfloat16* Ag, const __nv_bfloat16* Bg,
                                           uint32_t stage_base, int tid, int kit) {
    const __nv_bfloat16* Ak = Ag + kit * BK;
    const __nv_bfloat16* Bk = Bg + kit * BK;
    uint32_t sa = stage_base;
    uint32_t sbb = stage_base + 16384;
#pragma unroll
    for (int i = 0; i < 4; i++) {
        int u = tid + i * 256;          // 0..1023
        int row = u >> 3, c = u & 7;
        uint32_t off = swz((uint32_t)(row * 128 + c * 16));
        cp_async16(sa  + off, Ak + (size_t)row * KTOT + c * 8);
        cp_async16(sbb + off, Bk + (size_t)row * KTOT + c * 8);
    }
}

__global__ __launch_bounds__(256) void mma_gemm_kernel(
    const __nv_bfloat16* __restrict__ A, const __nv_bfloat16* __restrict__ B,
    float* __restrict__ C)
{
    extern __shared__ char smem[];
    const uint32_t sb = smem_u32(smem);
    const int tid = threadIdx.x, wid = tid >> 5, lane = tid & 31;
    const int m0 = blockIdx.y * 128;
    const int n0 = blockIdx.x * 128;
    const int warpM = (wid & 3) * 32;
    const int warpN = (wid >> 2) * 64;

    const __nv_bfloat16* Ag = A + (size_t)m0 * KTOT;
    const __nv_bfloat16* Bg = B + (size_t)n0 * KTOT;

    float acc[2][8][4];
#pragma unroll
    for (int mi = 0; mi < 2; mi++)
#pragma unroll
        for (int ni = 0; ni < 8; ni++)
#pragma unroll
            for (int q = 0; q < 4; q++) acc[mi][ni][q] = 0.f;

    // ldmatrix lane address components (row part fixed per lane)
    const int arow = warpM + (lane & 15);            // A: rows m
    const int brow = warpN + (lane & 7) + ((lane >> 4) << 3); // B: n, +8 for upper half
    const uint32_t acol_base = (uint32_t)((lane >> 4) << 4);       // 0 or 16 bytes
    const uint32_t bcol_base = (uint32_t)(((lane >> 3) & 1) << 4); // 0 or 16 bytes

#pragma unroll
    for (int s = 0; s < NSTG - 1; s++) { load_stage(Ag, Bg, sb + s * STG_BYTES, tid, s); CP_COMMIT(); }

    for (int it = 0; it < KI; it++) {
        if (it + NSTG - 1 < KI)
            load_stage(Ag, Bg, sb + ((it + NSTG - 1) & 3) * STG_BYTES, tid, it + NSTG - 1);
        CP_COMMIT();
        CP_WAIT(NSTG - 1);
        __syncthreads();

        const uint32_t sa  = sb + (it & 3) * STG_BYTES;
        const uint32_t sbb = sa + 16384;
#pragma unroll
        for (int kk = 0; kk < 4; kk++) {
            const uint32_t kByte = (uint32_t)(kk * 32);
            uint32_t a[2][4];
#pragma unroll
            for (int mi = 0; mi < 2; mi++) {
                uint32_t off = swz((uint32_t)((arow + mi * 16) * 128) + kByte + acol_base);
                ldsm_x4(a[mi][0], a[mi][1], a[mi][2], a[mi][3], sa + off);
            }
            uint32_t b[8][2];
#pragma unroll
            for (int nb = 0; nb < 4; nb++) {
                uint32_t off = swz((uint32_t)((brow + nb * 16) * 128) + kByte + bcol_base);
                uint32_t r0, r1, r2, r3;
                ldsm_x4(r0, r1, r2, r3, sbb + off);
                b[nb * 2][0] = r0; b[nb * 2][1] = r1;
                b[nb * 2 + 1][0] = r2; b[nb * 2 + 1][1] = r3;
            }
#pragma unroll
            for (int mi = 0; mi < 2; mi++)
#pragma unroll
                for (int ni = 0; ni < 8; ni++)
                    mma16816(acc[mi][ni][0], acc[mi][ni][1], acc[mi][ni][2], acc[mi][ni][3],
                             a[mi][0], a[mi][1], a[mi][2], a[mi][3], b[ni][0], b[ni][1]);
        }
        __syncthreads();
    }

    // epilogue: c frag -> C ;  c0,c1 at (row=t/4, col=2*(t%4)), c2,c3 at row+8
    const int crow = m0 + warpM + (lane >> 2);
    const int ccol = n0 + warpN + 2 * (lane & 3);
#pragma unroll
    for (int mi = 0; mi < 2; mi++)
#pragma unroll
        for (int ni = 0; ni < 8; ni++) {
            float* p0 = C + (size_t)(crow + mi * 16) * HID + ccol + ni * 8;
            float* p1 = p0 + 8 * HID;
            *reinterpret_cast<float2*>(p0) = make_float2(acc[mi][ni][0], acc[mi][ni][1]);
            *reinterpret_cast<float2*>(p1) = make_float2(acc[mi][ni][2], acc[mi][ni][3]);
        }
}

// ---------------- LayerNorm (warp per row) ----------------
__global__ __launch_bounds__(256) void ln_kernel(
    const float* __restrict__ xp, const float* __restrict__ ln_g,
    const float* __restrict__ ln_b, float* __restrict__ xn)
{
    int w = threadIdx.x >> 5, lane = threadIdx.x & 31;
    int row = blockIdx.x * 8 + w;
    const float4* xr = reinterpret_cast<const float4*>(xp + (size_t)row * HID);
    float4 v[8];
    float s = 0.f, s2 = 0.f;
#pragma unroll
    for (int i = 0; i < 8; i++) {
        v[i] = xr[lane + 32 * i];
        s  += v[i].x + v[i].y + v[i].z + v[i].w;
        s2 += v[i].x*v[i].x + v[i].y*v[i].y + v[i].z*v[i].z + v[i].w*v[i].w;
    }
#pragma unroll
    for (int o = 16; o > 0; o >>= 1) {
        s  += __shfl_xor_sync(0xffffffffu, s, o);
        s2 += __shfl_xor_sync(0xffffffffu, s2, o);
    }
    float mu = s * (1.f / HID);
    float rs = rsqrtf(s2 * (1.f / HID) - mu * mu + 1e-5f);
    float4* xo = reinterpret_cast<float4*>(xn + (size_t)row * HID);
#pragma unroll
    for (int i = 0; i < 8; i++) {
        int idx = lane + 32 * i;
        float4 g4 = reinterpret_cast<const float4*>(ln_g)[idx];
        float4 b4 = reinterpret_cast<const float4*>(ln_b)[idx];
        float4 o;
        o.x = (v[i].x - mu) * rs * g4.x + b4.x;
        o.y = (v[i].y - mu) * rs * g4.y + b4.y;
        o.z = (v[i].z - mu) * rs * g4.z + b4.z;
        o.w = (v[i].w - mu) * rs * g4.w + b4.w;
        xo[idx] = o;
    }
}

// ---------------- gates: [128 rows x 32 gates] per block, Wg tiled in SMEM ----------------
__global__ __launch_bounds__(256) void gates_kernel(
    const float* __restrict__ xn, const float* __restrict__ Wg,
    const float* __restrict__ bg, const float* __restrict__ eig,
    float* __restrict__ a_out, float* __restrict__ beta_out)
{
    __shared__ float As[32][128];
    __shared__ float Bs[32][32];
    const int tid = threadIdx.x;
    const int m0 = blockIdx.x * 128;
    const int tr = tid >> 4, tc = tid & 15;
    float acc[8][2];
#pragma unroll
    for (int i = 0; i < 8; i++) { acc[i][0] = 0.f; acc[i][1] = 0.f; }

    for (int k0 = 0; k0 < HID; k0 += 32) {
#pragma unroll
        for (int i = 0; i < 4; i++) {
            int u = tid + i * 256;
            int row = u >> 3, c4 = u & 7;
            float4 vv = *reinterpret_cast<const float4*>(xn + (size_t)(m0 + row) * HID + k0 + c4 * 4);
            As[c4*4+0][row] = vv.x; As[c4*4+1][row] = vv.y;
            As[c4*4+2][row] = vv.z; As[c4*4+3][row] = vv.w;
        }
        {
            int gr = tid >> 3, c4 = tid & 7;
            float4 vv = *reinterpret_cast<const float4*>(Wg + (size_t)gr * HID + k0 + c4 * 4);
            Bs[c4*4+0][gr] = vv.x; Bs[c4*4+1][gr] = vv.y;
            Bs[c4*4+2][gr] = vv.z; Bs[c4*4+3][gr] = vv.w;
        }
        __syncthreads();
#pragma unroll
        for (int k = 0; k < 32; k++) {
            float4 a0 = *reinterpret_cast<float4*>(&As[k][tr*8]);
            float4 a1 = *reinterpret_cast<float4*>(&As[k][tr*8+4]);
            float b0 = Bs[k][tc*2], b1 = Bs[k][tc*2+1];
            float rm[8] = {a0.x,a0.y,a0.z,a0.w,a1.x,a1.y,a1.z,a1.w};
#pragma unroll
            for (int i = 0; i < 8; i++) {
                acc[i][0] = fmaf(rm[i], b0, acc[i][0]);
                acc[i][1] = fmaf(rm[i], b1, acc[i][1]);
            }
        }
        __syncthreads();
    }
#pragma unroll
    for (int j = 0; j < 2; j++) {
        int g = tc * 2 + j;
        float bgv = bg[g];
#pragma unroll
        for (int i = 0; i < 8; i++) {
            int row = m0 + tr * 8 + i;
            float sg = 1.f / (1.f + expf(-(acc[i][j] + bgv)));
            if (g < 16) a_out[(size_t)row * NHEAD + g] = tanhf(eig[g]) * sg;
            else        beta_out[(size_t)row * NHEAD + (g - 16)] = sg;
        }
    }
}

// ---------------- scan pass 1: per-chunk contribution with reference masking ----------------
__global__ __launch_bounds__(64) void scan1_kernel(
    const float* __restrict__ a_buf, const float* __restrict__ beta_buf,
    const float* __restrict__ xn,
    float* __restrict__ contrib, float* __restrict__ cum_out,
    float* __restrict__ Cc, float* __restrict__ Ee)
{
    const int blk = blockIdx.x;
    const int h   = blk & 15;
    const int bn  = blk >> 4;
    const int base_pos = bn * CSZ;
    const int d = threadIdx.x;

    __shared__ float s_a[CSZ], s_cum[CSZ], s_inv[CSZ], s_beta[CSZ];
    if (d < CSZ) {
        s_a[d]    = a_buf[(size_t)(base_pos + d) * NHEAD + h];
        s_beta[d] = beta_buf[(size_t)(base_pos + d) * NHEAD + h];
    }
    __syncthreads();
    if (d == 0) {
        float c = 1.f;
#pragma unroll
        for (int j = 0; j < CSZ; j++) {
            float cp = c;
            c = c * s_a[j];
            s_cum[j] = c;
            s_inv[j] = (fabsf(cp) > 1e-8f) ? (1.f / cp) : 0.f;
        }
    }
    __syncthreads();
    if (d < CSZ) cum_out[(size_t)(base_pos + d) * NHEAD + h] = s_cum[d];

    float Q = 0.f, hc = 0.f;
#pragma unroll
    for (int j = 0; j < CSZ; j++) {
        size_t idx = (size_t)(base_pos + j) * HID + h * HD + d;
        float bv = s_beta[j] * xn[idx];
        hc = fmaf(s_cum[j], Q, bv);
        contrib[idx] = hc;
        Q = fmaf(bv, s_inv[j], Q);
    }
    Ee[(size_t)bn * HID + h * HD + d] = hc;
    if (d == 0) Cc[(size_t)bn * NHEAD + h] = s_cum[CSZ - 1];
}

// ---------------- scan pass 2: 3-phase group scan over 256 chunks ----------------
__global__ __launch_bounds__(256) void scan2a_kernel(
    const float* __restrict__ Cc, const float* __restrict__ Ee,
    float* __restrict__ P2, float* __restrict__ E2)
{
    int idx = blockIdx.x * 256 + threadIdx.x;   // 65536
    int ch = idx & 4095, grp = idx >> 12;
    int b = ch >> 10, c = ch & 1023, h = c >> 6;
    float P = 1.f, E = 0.f;
#pragma unroll
    for (int i = 0; i < 16; i++) {
        int bn = b * NCHUNK + grp * 16 + i;
        float cc = Cc[(size_t)bn * NHEAD + h];
        E = fmaf(cc, E, Ee[(size_t)bn * HID + c]);
        P *= cc;
    }
    P2[idx] = P; E2[idx] = E;
}
__global__ __launch_bounds__(128) void scan2b_kernel(
    const float* __restrict__ P2, const float* __restrict__ E2, float* __restrict__ G2)
{
    int ch = blockIdx.x * 128 + threadIdx.x;    // 4096
    float car = 0.f;
#pragma unroll
    for (int g = 0; g < 16; g++) {
        G2[g * 4096 + ch] = car;
        car = fmaf(P2[g * 4096 + ch], car, E2[g * 4096 + ch]);
    }
}
__global__ __launch_bounds__(256) void scan2c_kernel(
    const float* __restrict__ Cc, const float* __restrict__ Ee,
    const float* __restrict__ G2, float* __restrict__ carry)
{
    int idx = blockIdx.x * 256 + threadIdx.x;
    int ch = idx & 4095, grp = idx >> 12;
    int b = ch >> 10, c = ch & 1023, h = c >> 6;
    float car = G2[grp * 4096 + ch];
#pragma unroll
    for (int i = 0; i < 16; i++) {
        int bn = b * NCHUNK + grp * 16 + i;
        carry[(size_t)bn * HID + c] = car;
        car = fmaf(Cc[(size_t)bn * NHEAD + h], car, Ee[(size_t)bn * HID + c]);
    }
}

// ---------------- scan pass 3: h = cum*carry + contrib -> bf16 triplet + h_final ----------------
__global__ __launch_bounds__(256) void scan3_kernel(
    const float* __restrict__ cum, const float* __restrict__ carry,
    const float* __restrict__ contrib,
    __nv_bfloat16* __restrict__ Abuf, float* __restrict__ h_final)
{
    int g = blockIdx.x * 256 + threadIdx.x;     // float4 index
    int pos = g >> 8;
    int c0  = (g & 255) << 2;
    int h   = c0 >> 6;
    int bn  = pos >> 4;

    float cm = cum[(size_t)pos * NHEAD + h];
    float4 cr = reinterpret_cast<const float4*>(carry + (size_t)bn * HID)[c0 >> 2];
    float4 hv = reinterpret_cast<const float4*>(contrib)[g];
    hv.x = fmaf(cm, cr.x, hv.x);
    hv.y = fmaf(cm, cr.y, hv.y);
    hv.z = fmaf(cm, cr.z, hv.z);
    hv.w = fmaf(cm, cr.w, hv.w);

    float f[4] = {hv.x, hv.y, hv.z, hv.w};
    union { __nv_bfloat16 b[4]; uint2 u; } H, L;
#pragma unroll
    for (int i = 0; i < 4; i++) {
        H.b[i] = __float2bfloat16_rn(f[i]);
        L.b[i] = __float2bfloat16_rn(f[i] - __bfloat162float(H.b[i]));
    }
    size_t base = (size_t)pos * KTOT + c0;
    *reinterpret_cast<uint2*>(Abuf + base)        = H.u;
    *reinterpret_cast<uint2*>(Abuf + base + 1024) = L.u;
    *reinterpret_cast<uint2*>(Abuf + base + 2048) = H.u;

    if ((pos & (SEQ - 1)) == SEQ - 1) {
        int b = pos >> 12;
        reinterpret_cast<float4*>(h_final + (size_t)b * HID)[c0 >> 2] = hv;
    }
}

// ---------------- launch ----------------
extern "C" void kernel_launch(void* const* d_in, const int* in_sizes, int n_in,
                              void* d_out, int out_size)
{
    const float* x       = (const float*)d_in[0];
    const float* W_in    = (const float*)d_in[1];
    const float* ln_g    = (const float*)d_in[2];
    const float* ln_b    = (const float*)d_in[3];
    const float* W_gate  = (const float*)d_in[4];
    const float* b_gate  = (const float*)d_in[5];
    const float* eig_raw = (const float*)d_in[6];
    const float* W_out   = (const float*)d_in[7];

    float* out     = (float*)d_out;
    float* h_final = out + (size_t)MROWS * HID;

    __nv_bfloat16 *Abuf, *Bbuf;
    float *xp, *xn, *contrib, *ab, *bb, *cum, *Cc, *Ee, *carry, *P2, *E2, *G2;
    cudaGetSymbolAddress((void**)&Abuf,    g_Abuf);
    cudaGetSymbolAddress((void**)&Bbuf,    g_Bbuf);
    cudaGetSymbolAddress((void**)&xp,      g_xp);
    cudaGetSymbolAddress((void**)&xn,      g_xn);
    cudaGetSymbolAddress((void**)&contrib, g_contrib);
    cudaGetSymbolAddress((void**)&ab,      g_a);
    cudaGetSymbolAddress((void**)&bb,      g_beta);
    cudaGetSymbolAddress((void**)&cum,     g_cum);
    cudaGetSymbolAddress((void**)&Cc,      g_C);
    cudaGetSymbolAddress((void**)&Ee,      g_E);
    cudaGetSymbolAddress((void**)&carry,   g_carry);
    cudaGetSymbolAddress((void**)&P2,      g_P2);
    cudaGetSymbolAddress((void**)&E2,      g_E2);
    cudaGetSymbolAddress((void**)&G2,      g_G2);

    cudaFuncSetAttribute(mma_gemm_kernel, cudaFuncAttributeMaxDynamicSharedMemorySize, GEMM_SMEM);

    // 1) convert x and W_in to bf16 split triplets, GEMM1 -> xp
    convert_tri_kernel<0><<<MROWS, 256>>>(x, Abuf);
    convert_tri_kernel<1><<<HID, 256>>>(W_in, Bbuf);
    mma_gemm_kernel<<<dim3(HID / 128, MROWS / 128), 256, GEMM_SMEM>>>(Abuf, Bbuf, xp);

    // 2) LN, gates
    ln_kernel<<<MROWS / 8, 256>>>(xp, ln_g, ln_b, xn);
    gates_kernel<<<MROWS / 128, 256>>>(xn, W_gate, b_gate, eig_raw, ab, bb);

    // 3) chunked scan (reference masking) -> bf16 triplet of h_all + h_final
    scan1_kernel<<<BNCH * NHEAD, 64>>>(ab, bb, xn, contrib, cum, Cc, Ee);
    scan2a_kernel<<<(BATCH * HID * 16) / 256, 256>>>(Cc, Ee, P2, E2);
    scan2b_kernel<<<(BATCH * HID) / 128, 128>>>(P2, E2, G2);
    scan2c_kernel<<<(BATCH * HID * 16) / 256, 256>>>(Cc, Ee, G2, carry);
    scan3_kernel<<<MROWS, 256>>>(cum, carry, contrib, Abuf, h_final);

    // 4) GEMM2 -> out
    convert_tri_kernel<1><<<HID, 256>>>(W_out, Bbuf);
    mma_gemm_kernel<<<dim3(HID / 128, MROWS / 128), 256, GEMM_SMEM>>>(Abuf, Bbuf, out);
}